// round 14
// baseline (speedup 1.0000x reference)
#include <cuda_runtime.h>
#include <cuda_bf16.h>
#include <stdint.h>
#include <math.h>

#define NN 3072
#define HH 256
#define HD 64
#define NHID (NN*HH)
#define NSPLIT 3
#define ZRANGE (NN/NSPLIT)   // 1024
#define ZTILE 32
#define NZI (ZRANGE/ZTILE)   // 32
#define SCALE 0.125f         // HD^-0.5
#define PSTRIDE 72

// ---------------- device scratch (static; no allocations) ----------------
__device__ __nv_bfloat16 g_hnB[NHID];
__device__ __nv_bfloat16 g_hnT[HH*NN];
__device__ __nv_bfloat16 g_kt[4*NN*HD];
__device__ __nv_bfloat16 g_mut[4*NN*HD];
__device__ __nv_bfloat16 g_lst[4*NN*HD];
__device__ __nv_bfloat16 g_WT[3*HH*HH];
__device__ __nv_bfloat16 g_WvT[16*256*PSTRIDE];       // kc-blocked padded for bulk final
__device__ float g_acc[(size_t)NN*1024];
__device__ float g_den[NN*4];
__device__ double g_kl;

// ---------------- PTX helpers ----------------
__device__ __forceinline__ void mma16816(float d[4], const uint32_t a[4],
                                         uint32_t b0, uint32_t b1) {
    asm volatile(
        "mma.sync.aligned.m16n8k16.row.col.f32.bf16.bf16.f32 "
        "{%0,%1,%2,%3},{%4,%5,%6,%7},{%8,%9},{%0,%1,%2,%3};\n"
        : "+f"(d[0]), "+f"(d[1]), "+f"(d[2]), "+f"(d[3])
        : "r"(a[0]), "r"(a[1]), "r"(a[2]), "r"(a[3]), "r"(b0), "r"(b1));
}
__device__ __forceinline__ void ldsm4(uint32_t r[4], uint32_t saddr) {
    asm volatile("ldmatrix.sync.aligned.m8n8.x4.shared.b16 {%0,%1,%2,%3}, [%4];\n"
        : "=r"(r[0]), "=r"(r[1]), "=r"(r[2]), "=r"(r[3]) : "r"(saddr));
}
__device__ __forceinline__ void cp16(uint32_t saddr, const void* g) {
    asm volatile("cp.async.cg.shared.global [%0], [%1], 16;\n" :: "r"(saddr), "l"(g));
}
#define CP_COMMIT() asm volatile("cp.async.commit_group;\n" ::: "memory")
#define CP_WAIT(n)  asm volatile("cp.async.wait_group %0;\n" :: "n"(n) : "memory")
__device__ __forceinline__ uint32_t s32(const void* p) {
    return (uint32_t)__cvta_generic_to_shared(p);
}
__device__ __forceinline__ void bulkcp(uint32_t dst, const void* src, uint32_t bytes,
                                       uint32_t mbar) {
    asm volatile("cp.async.bulk.shared::cluster.global.mbarrier::complete_tx::bytes "
                 "[%0], [%1], %2, [%3];\n"
                 :: "r"(dst), "l"(src), "r"(bytes), "r"(mbar) : "memory");
}
__device__ __forceinline__ void mbar_init(uint32_t m, uint32_t cnt) {
    asm volatile("mbarrier.init.shared.b64 [%0], %1;\n" :: "r"(m), "r"(cnt) : "memory");
}
__device__ __forceinline__ void mbar_expect(uint32_t m, uint32_t bytes) {
    asm volatile("mbarrier.arrive.expect_tx.shared.b64 _, [%0], %1;\n"
                 :: "r"(m), "r"(bytes) : "memory");
}
__device__ __forceinline__ void mbar_wait(uint32_t m, uint32_t parity) {
    uint32_t done;
    do {
        asm volatile("{\n.reg .pred p;\n"
                     "mbarrier.try_wait.parity.acquire.cta.shared::cta.b64 p, [%1], %2, 0x989680;\n"
                     "selp.b32 %0,1,0,p;\n}"
                     : "=r"(done) : "r"(m), "r"(parity) : "memory");
    } while (!done);
}
// softplus(s) for |s|<~1.2 (scores are N(0,0.105), max ~0.6): Taylor to s^6, err<3e-5
__device__ __forceinline__ float softplus_poly(float s) {
    float s2 = s*s;
    return fmaf(s2, fmaf(s2, fmaf(s2, 3.472222e-4f, -5.208333e-3f), 0.125f),
                fmaf(0.5f, s, 0.69314718f));
}
// log(softplus(s)), same range, err<6e-5 at |s|=1
__device__ __forceinline__ float logsoftplus_poly(float s) {
    return fmaf(s, fmaf(s, fmaf(s, fmaf(s, fmaf(s, fmaf(s, -1.3840e-4f, 2.5020e-4f),
            2.3785e-3f), -4.9730e-3f), -7.98342e-2f), 0.7213475f), -0.36651292f);
}

// ---------------- prep: LayerNorm + weight transposes + accumulator zeroing ----------------
__global__ void __launch_bounds__(256) prep_kernel(const float* __restrict__ h,
                                                   const float* __restrict__ gamma,
                                                   const float* __restrict__ beta,
                                                   const float* __restrict__ Wk,
                                                   const float* __restrict__ Wm,
                                                   const float* __restrict__ Wl,
                                                   const float* __restrict__ Wv) {
    __shared__ float sh[32][33];
    int bx = blockIdx.x, t = threadIdx.x;
    if (bx < NN) {
        int n = bx;
        *(float4*)(g_acc + (size_t)n*1024 + t*4) = make_float4(0.f,0.f,0.f,0.f);
        if (t == 0) *(float4*)(g_den + n*4) = make_float4(0.f,0.f,0.f,0.f);
        float v = h[n*HH + t];
        float s = v, q = v*v;
        #pragma unroll
        for (int o = 16; o; o >>= 1) {
            s += __shfl_down_sync(0xffffffffu, s, o);
            q += __shfl_down_sync(0xffffffffu, q, o);
        }
        __shared__ float ss[8], qs[8];
        __shared__ float s_m, s_r;
        int lane = t & 31, w = t >> 5;
        if (lane == 0) { ss[w] = s; qs[w] = q; }
        __syncthreads();
        if (t == 0) {
            float S = 0.f, Q = 0.f;
            #pragma unroll
            for (int i = 0; i < 8; i++) { S += ss[i]; Q += qs[i]; }
            float m = S * (1.f/256.f);
            float var = Q * (1.f/256.f) - m*m;
            s_m = m; s_r = rsqrtf(var + 1e-5f);
        }
        __syncthreads();
        float hn = (v - s_m) * s_r * gamma[t] + beta[t];
        __nv_bfloat16 hb = __float2bfloat16(hn);
        g_hnB[(size_t)n*HH + t] = hb;
        g_hnT[(size_t)t*NN + n] = hb;
        if (n == 0 && t == 0) g_kl = 0.0;
    } else {
        int tb = bx - NN;
        int tx = t & 31, ty = t >> 5;
        if (tb < 192) {
            int p = tb >> 6, tl = tb & 63;
            const float* src = (p == 0) ? Wk : (p == 1) ? Wm : Wl;
            __nv_bfloat16* dst = g_WT + (size_t)p*HH*HH;
            int o0 = (tl & 7)*32, k0 = (tl >> 3)*32;
            #pragma unroll
            for (int j = 0; j < 32; j += 8)
                sh[ty+j][tx] = src[(size_t)(k0+ty+j)*HH + o0+tx];
            __syncthreads();
            #pragma unroll
            for (int j = 0; j < 32; j += 8)
                dst[(size_t)(o0+ty+j)*HH + k0+tx] = __float2bfloat16(sh[tx][ty+j]);
        } else {
            int tl = tb - 192;
            int o0 = (tl & 7)*32, k0 = (tl >> 3)*32;
            #pragma unroll
            for (int j = 0; j < 32; j += 8)
                sh[ty+j][tx] = Wv[(size_t)(k0+ty+j)*HH + o0+tx];
            __syncthreads();
            #pragma unroll
            for (int j = 0; j < 32; j += 8) {
                int o = o0+ty+j, k = k0+tx;
                g_WvT[(size_t)(k >> 6)*(256*PSTRIDE) + o*PSTRIDE + (k & 63)] =
                    __float2bfloat16(sh[tx][ty+j]);
            }
        }
    }
}

// ---------------- 3 projections (bf16 HMMA) -> head-transposed bf16 ----------------
#define PROJ_SMEM ((64*264 + 256*72)*2)
__global__ void __launch_bounds__(256) proj_kernel(const float* __restrict__ bk,
                                                   const float* __restrict__ bm,
                                                   const float* __restrict__ bl) {
    extern __shared__ __nv_bfloat16 ps[];
    __nv_bfloat16* a_s = ps;
    __nv_bfloat16* b_s = ps + 64*264;
    int p = blockIdx.y;
    const __nv_bfloat16* WT = g_WT + (size_t)p*HH*HH;
    const float* bi = (p == 0) ? bk : (p == 1) ? bm : bl;
    __nv_bfloat16* dst = (p == 0) ? g_kt : (p == 1) ? g_mut : g_lst;
    int tid = threadIdx.x;
    int r0 = blockIdx.x * 64;

    #pragma unroll
    for (int j = 0; j < 8; j++) {
        int idx = j*256 + tid; int row = idx >> 5, u = idx & 31;
        *(uint4*)(a_s + row*264 + u*8) =
            *(const uint4*)(g_hnB + (size_t)(r0+row)*HH + u*8);
    }

    int w = tid >> 5, l = tid & 31, t2 = (l & 3)*2, g = l >> 2;
    int wm = w >> 1, wn = w & 1;
    uint32_t a_base = s32(a_s) + (uint32_t)(((wm*16 + (l & 15))*264 + (l >> 4)*8) * 2);
    uint32_t b_base = s32(b_s) + (uint32_t)((((l >> 4)*8 + (l & 7))*72 + ((l >> 3) & 1)*8) * 2);
    float acc[16][4];
    #pragma unroll
    for (int nt = 0; nt < 16; nt++) { acc[nt][0]=0.f; acc[nt][1]=0.f; acc[nt][2]=0.f; acc[nt][3]=0.f; }

    for (int kc = 0; kc < 4; kc++) {
        __syncthreads();
        #pragma unroll
        for (int j = 0; j < 8; j++) {
            int idx = j*256 + tid; int o = idx >> 3, u = idx & 7;
            *(uint4*)(b_s + o*72 + u*8) =
                *(const uint4*)(WT + (size_t)o*HH + kc*64 + u*8);
        }
        __syncthreads();
        #pragma unroll
        for (int k16 = 0; k16 < 4; k16++) {
            uint32_t a[4];
            ldsm4(a, a_base + (uint32_t)((kc*64 + k16*16)*2));
            #pragma unroll
            for (int ntp = 0; ntp < 8; ntp++) {
                uint32_t bb[4];
                ldsm4(bb, b_base + (uint32_t)(((wn*128 + ntp*16)*72 + k16*16)*2));
                mma16816(acc[ntp*2],   a, bb[0], bb[1]);
                mma16816(acc[ntp*2+1], a, bb[2], bb[3]);
            }
        }
    }

    #pragma unroll
    for (int nt = 0; nt < 16; nt++) {
        int oc = wn*128 + nt*8 + t2;
        float b0v = bi[oc], b1v = bi[oc+1];
        int m0 = r0 + wm*16 + g, m1 = m0 + 8;
        dst[((size_t)(oc & 3)*NN + m0)*HD + (oc >> 2)]         = __float2bfloat16(acc[nt][0] + b0v);
        dst[((size_t)((oc+1) & 3)*NN + m0)*HD + ((oc+1) >> 2)] = __float2bfloat16(acc[nt][1] + b1v);
        dst[((size_t)(oc & 3)*NN + m1)*HD + (oc >> 2)]         = __float2bfloat16(acc[nt][2] + b0v);
        dst[((size_t)((oc+1) & 3)*NN + m1)*HD + ((oc+1) >> 2)] = __float2bfloat16(acc[nt][3] + b1v);
    }
}

// ---------------- fused attention: champion + polynomial softplus ----------------
#define K_S_ELEMS  (4*32*72)
#define MU_BUF     (4*ZTILE*72)
#define HN_STRIDE  40
#define HN_BUF     (256*HN_STRIDE)
#define AF_BUF     (128*40)
#define BF_ELEMS   (K_S_ELEMS + 2*MU_BUF + 2*MU_BUF + 2*HN_BUF + AF_BUF)
#define EPS_STRIDE 132
#define DIF_STRIDE 36
#define EPS_BUF (32*EPS_STRIDE)
#define DIF_BUF (32*DIF_STRIDE)
#define ATTN_SMEM_BYTES (BF_ELEMS*2 + (2*EPS_BUF + 2*DIF_BUF)*4)

__global__ void __launch_bounds__(256, 1) attn_kernel(const float* __restrict__ diff,
                                                      const float* __restrict__ eps) {
    extern __shared__ __nv_bfloat16 smb[];
    __nv_bfloat16* k_s  = smb;
    __nv_bfloat16* mu_s = k_s + K_S_ELEMS;
    __nv_bfloat16* ls_s = mu_s + 2*MU_BUF;
    __nv_bfloat16* hn_s = ls_s + 2*MU_BUF;
    float* eps_s = (float*)(smb + BF_ELEMS);
    float* dif_s = eps_s + 2*EPS_BUF;
    __shared__ float red[8];

    const int tid = threadIdx.x;
    const int xt = blockIdx.x / NSPLIT, sp = blockIdx.x % NSPLIT;
    const int x0 = xt * 32, zbase = sp * ZRANGE;
    const int w = tid >> 5, l = tid & 31;
    const int b = w >> 1, xh = w & 1;
    const int g = l >> 2, t2 = (l & 3) * 2;

    const uint32_t mu_fb = s32(mu_s) + (uint32_t)(((b*32 + (l & 7))*72 + (l >> 3)*8) * 2);
    const uint32_t ls_fb = s32(ls_s) + (uint32_t)(((b*32 + (l & 7))*72 + (l >> 3)*8) * 2);
    const uint32_t hn_fb = s32(hn_s) + (uint32_t)((((l >> 4)*8 + (l & 7))*HN_STRIDE + ((l >> 3) & 1)*8) * 2);

    auto stage = [&](int zb, int cb) {
        __nv_bfloat16* mb_ = mu_s + cb*MU_BUF;
        __nv_bfloat16* lb_ = ls_s + cb*MU_BUF;
        __nv_bfloat16* hb_ = hn_s + cb*HN_BUF;
        float* eb_ = eps_s + cb*EPS_BUF;
        float* db_ = dif_s + cb*DIF_BUF;
        #pragma unroll
        for (int j = 0; j < 4; j++) {
            int idx = j*256 + tid; int row = idx >> 3, u = idx & 7;
            int bb_ = row >> 5, z_ = row & 31;
            cp16(s32(mb_ + row*72 + u*8), g_mut + ((size_t)bb_*NN + zb + z_)*HD + u*8);
            cp16(s32(lb_ + row*72 + u*8), g_lst + ((size_t)bb_*NN + zb + z_)*HD + u*8);
        }
        #pragma unroll
        for (int j = 0; j < 4; j++) {
            int idx = j*256 + tid; int row = idx >> 2, u = idx & 3;
            cp16(s32(hb_ + row*HN_STRIDE + u*8), g_hnT + (size_t)row*NN + zb + u*8);
        }
        #pragma unroll
        for (int j = 0; j < 4; j++) {
            int idx = j*256 + tid; int x = idx >> 5, u = idx & 31;
            cp16(s32(eb_ + x*EPS_STRIDE + u*4), eps + ((size_t)(x0+x)*NN + zb)*4 + u*4);
        }
        {
            int x = tid >> 3, u = tid & 7;
            cp16(s32(db_ + x*DIF_STRIDE + u*4), diff + (size_t)(x0+x)*NN + zb + u*4);
        }
    };

    #pragma unroll
    for (int j = 0; j < 4; j++) {
        int idx = j*256 + tid; int row = idx >> 3, u = idx & 7;
        int br = row >> 5, xr = row & 31;
        cp16(s32(k_s + (br*32 + xr)*72 + u*8),
             g_kt + ((size_t)br*NN + x0 + xr)*HD + u*8);
    }
    stage(zbase, 0);
    CP_COMMIT();

    float acc[32][4];
    #pragma unroll
    for (int nt = 0; nt < 32; nt++) { acc[nt][0]=0.f; acc[nt][1]=0.f; acc[nt][2]=0.f; acc[nt][3]=0.f; }
    float den0 = 0.f, den1 = 0.f, klloc = 0.f;
    uint32_t kfr[4][4];

    for (int zi = 0; zi < NZI; ++zi) {
        __syncthreads();
        if (zi + 1 < NZI) {
            stage(zbase + (zi+1)*ZTILE, (zi+1) & 1);
            CP_COMMIT();
            CP_WAIT(1);
        } else {
            CP_WAIT(0);
        }
        __syncthreads();

        if (zi == 0) {
            #pragma unroll
            for (int kt = 0; kt < 4; kt++) {
                const __nv_bfloat16* base = k_s + (b*32 + xh*16)*72 + kt*16;
                kfr[kt][0] = *(const uint32_t*)(base + (size_t)g*72     + t2);
                kfr[kt][1] = *(const uint32_t*)(base + (size_t)(g+8)*72 + t2);
                kfr[kt][2] = *(const uint32_t*)(base + (size_t)g*72     + t2 + 8);
                kfr[kt][3] = *(const uint32_t*)(base + (size_t)(g+8)*72 + t2 + 8);
            }
        }
        const int cb = zi & 1;
        const float* ecur = eps_s + cb*EPS_BUF;
        const float* dcur = dif_s + cb*DIF_BUF;
        const uint32_t mu_base = mu_fb + (uint32_t)((cb*MU_BUF)*2);
        const uint32_t ls_base = ls_fb + (uint32_t)((cb*MU_BUF)*2);
        const uint32_t hn_base = hn_fb + (uint32_t)((cb*HN_BUF)*2);

        #pragma unroll
        for (int zk = 0; zk < 2; zk++) {
            float dmu[2][4], dls[2][4];
            #pragma unroll
            for (int t = 0; t < 2; t++) {
                dmu[t][0]=0.f; dmu[t][1]=0.f; dmu[t][2]=0.f; dmu[t][3]=0.f;
                dls[t][0]=0.f; dls[t][1]=0.f; dls[t][2]=0.f; dls[t][3]=0.f;
                uint32_t roff = (uint32_t)(((zk*16 + t*8)*72) * 2);
                uint32_t mb[4], lb[4];
                ldsm4(mb, mu_base + roff);
                mma16816(dmu[t], kfr[0], mb[0], mb[1]);
                mma16816(dmu[t], kfr[1], mb[2], mb[3]);
                ldsm4(mb, mu_base + roff + 64);
                mma16816(dmu[t], kfr[2], mb[0], mb[1]);
                mma16816(dmu[t], kfr[3], mb[2], mb[3]);
                ldsm4(lb, ls_base + roff);
                mma16816(dls[t], kfr[0], lb[0], lb[1]);
                mma16816(dls[t], kfr[1], lb[2], lb[3]);
                ldsm4(lb, ls_base + roff + 64);
                mma16816(dls[t], kfr[2], lb[0], lb[1]);
                mma16816(dls[t], kfr[3], lb[2], lb[3]);
            }
            uint32_t af[4];
            #pragma unroll
            for (int t = 0; t < 2; t++) {
                #pragma unroll
                for (int rr = 0; rr < 2; rr++) {
                    int lx = xh*16 + rr*8 + g;
                    int lz = zk*16 + t*8 + t2;
                    float2 dv = *(const float2*)(dcur + lx*DIF_STRIDE + lz);
                    const float* ep = ecur + lx*EPS_STRIDE + lz*4 + b;
                    float e0 = ep[0], e1 = ep[4];
                    float m0 = dmu[t][rr*2]   * SCALE;
                    float m1 = dmu[t][rr*2+1] * SCALE;
                    float s0 = dls[t][rr*2]   * SCALE;
                    float s1 = dls[t][rr*2+1] * SCALE;
                    float sg0 = softplus_poly(s0);
                    float sg1 = softplus_poly(s1);
                    float lg0 = logsoftplus_poly(s0);
                    float lg1 = logsoftplus_poly(s1);
                    float d0 = dv.x, d1 = dv.y;
                    float a0 = __expf(fmaf(sg0, e0, m0)) * d0;
                    float a1 = __expf(fmaf(sg1, e1, m1)) * d1;
                    float sn0 = (d0 > 0.f) ? 1.f : ((d0 < 0.f) ? -1.f : 0.f);
                    float sn1 = (d1 > 0.f) ? 1.f : ((d1 < 0.f) ? -1.f : 0.f);
                    klloc += sn0 * (0.5f*(sg0*sg0 + m0*m0) - 0.5f - lg0);
                    klloc += sn1 * (0.5f*(sg1*sg1 + m1*m1) - 0.5f - lg1);
                    if (rr == 0) den0 += a0 + a1; else den1 += a0 + a1;
                    __nv_bfloat162 p = __float22bfloat162_rn(make_float2(a0, a1));
                    af[t*2 + rr] = *(uint32_t*)&p;
                }
            }
            #pragma unroll
            for (int ntp = 0; ntp < 16; ntp++) {
                uint32_t hb[4];
                ldsm4(hb, hn_base + (uint32_t)((ntp*16*HN_STRIDE + zk*16)*2));
                mma16816(acc[ntp*2],     af, hb[0], hb[1]);
                mma16816(acc[ntp*2 + 1], af, hb[2], hb[3]);
            }
        }
    }

    {
        const int xr_lo = x0 + xh*16 + g;
        float* outlo = g_acc + (size_t)xr_lo*1024 + b*256;
        float* outhi = outlo + (size_t)8*1024;
        #pragma unroll
        for (int nt = 0; nt < 32; nt++) {
            atomicAdd(outlo + nt*8 + t2,     acc[nt][0]);
            atomicAdd(outlo + nt*8 + t2 + 1, acc[nt][1]);
            atomicAdd(outhi + nt*8 + t2,     acc[nt][2]);
            atomicAdd(outhi + nt*8 + t2 + 1, acc[nt][3]);
        }
        den0 += __shfl_xor_sync(0xffffffffu, den0, 1);
        den0 += __shfl_xor_sync(0xffffffffu, den0, 2);
        den1 += __shfl_xor_sync(0xffffffffu, den1, 1);
        den1 += __shfl_xor_sync(0xffffffffu, den1, 2);
        if ((l & 3) == 0) {
            atomicAdd(g_den + (x0 + xh*16 + g)*4 + b,     den0);
            atomicAdd(g_den + (x0 + xh*16 + 8 + g)*4 + b, den1);
        }
    }
    #pragma unroll
    for (int o = 16; o; o >>= 1) klloc += __shfl_down_sync(0xffffffffu, klloc, o);
    if (l == 0) red[w] = klloc;
    __syncthreads();
    if (tid == 0) {
        float s = 0.f;
        #pragma unroll
        for (int i = 0; i < 8; i++) s += red[i];
        atomicAdd(&g_kl, (double)s);
    }
}

// ---------------- normalize + fc_v (bf16 HMMA, bulk W_v staging) ----------------
#define WV_BUF (256*72)
#define FIN_SMEM ((16*1032 + 2*WV_BUF)*2)
__global__ void __launch_bounds__(256) final_kernel(const float* __restrict__ bv,
                                                    const float* __restrict__ h0,
                                                    float* __restrict__ out,
                                                    int out_size) {
    extern __shared__ __nv_bfloat16 fs[];
    __nv_bfloat16* vsb  = fs;
    __nv_bfloat16* wv_s = fs + 16*1032;
    __shared__ alignas(8) uint64_t fmbar[2];
    int tid = threadIdx.x;
    int r0 = blockIdx.x * 16;
    const uint32_t mb0 = s32(&fmbar[0]), mb1 = s32(&fmbar[1]);

    if (tid == 0) { mbar_init(mb0, 1); mbar_init(mb1, 1); }
    __syncthreads();
    if (tid == 0) {
        mbar_expect(mb0, 36864);
        bulkcp(s32(wv_s), g_WvT, 36864, mb0);
    }

    #pragma unroll
    for (int ii = 0; ii < 16; ii++) {
        int idx = ii*256 + tid;
        int r = idx >> 8, c4 = idx & 255;
        int n = r0 + r;
        float4 a0 = *((const float4*)(g_acc + (size_t)n*1024) + c4);
        int b = c4 >> 6;
        float inv = 1.f / fmaxf(g_den[n*4 + b], 1e-12f);
        __nv_bfloat162 p0 = __float22bfloat162_rn(make_float2(a0.x*inv, a0.y*inv));
        __nv_bfloat162 p1 = __float22bfloat162_rn(make_float2(a0.z*inv, a0.w*inv));
        *(uint32_t*)(vsb + r*1032 + c4*4)     = *(uint32_t*)&p0;
        *(uint32_t*)(vsb + r*1032 + c4*4 + 2) = *(uint32_t*)&p1;
    }

    int w = tid >> 5, l = tid & 31, g = l >> 2, t2 = (l & 3)*2;
    int n0 = w * 32;
    uint32_t a_base = s32(vsb)  + (uint32_t)(((l & 15)*1032 + (l >> 4)*8) * 2);
    uint32_t b_base = s32(wv_s) + (uint32_t)((((l >> 4)*8 + (l & 7))*72 + ((l >> 3) & 1)*8) * 2);
    float acc[4][4];
    #pragma unroll
    for (int nt = 0; nt < 4; nt++) { acc[nt][0]=0.f; acc[nt][1]=0.f; acc[nt][2]=0.f; acc[nt][3]=0.f; }

    __syncthreads();

    for (int kc = 0; kc < 16; kc++) {
        __syncthreads();
        if (tid == 0 && kc + 1 < 16) {
            uint32_t m = ((kc+1) & 1) ? mb1 : mb0;
            mbar_expect(m, 36864);
            bulkcp(s32(wv_s + ((kc+1) & 1)*WV_BUF), g_WvT + (size_t)(kc+1)*WV_BUF, 36864, m);
        }
        mbar_wait((kc & 1) ? mb1 : mb0, (kc >> 1) & 1);

        uint32_t boff = (uint32_t)(((kc & 1)*WV_BUF)*2);
        #pragma unroll
        for (int k16 = 0; k16 < 4; k16++) {
            uint32_t a[4];
            ldsm4(a, a_base + (uint32_t)((kc*64 + k16*16)*2));
            #pragma unroll
            for (int ntp = 0; ntp < 2; ntp++) {
                uint32_t bb[4];
                ldsm4(bb, b_base + boff + (uint32_t)(((n0 + ntp*16)*72 + k16*16)*2));
                mma16816(acc[ntp*2],   a, bb[0], bb[1]);
                mma16816(acc[ntp*2+1], a, bb[2], bb[3]);
            }
        }
    }

    #pragma unroll
    for (int nt = 0; nt < 4; nt++) {
        int oc = n0 + nt*8 + t2;
        float b0v = bv[oc], b1v = bv[oc+1];
        int m0 = r0 + g, m1 = m0 + 8;
        float u00 = acc[nt][0] + b0v, u01 = acc[nt][1] + b1v;
        float u10 = acc[nt][2] + b0v, u11 = acc[nt][3] + b1v;
        u00 = (u00 > 0.f) ? u00 : expm1f(u00);
        u01 = (u01 > 0.f) ? u01 : expm1f(u01);
        u10 = (u10 > 0.f) ? u10 : expm1f(u10);
        u11 = (u11 > 0.f) ? u11 : expm1f(u11);
        float2 hv0 = *(const float2*)(h0 + (size_t)m0*HH + oc);
        float2 hv1 = *(const float2*)(h0 + (size_t)m1*HH + oc);
        *(float2*)(out + (size_t)m0*HH + oc) = make_float2(u00 + hv0.x, u01 + hv0.y);
        *(float2*)(out + (size_t)m1*HH + oc) = make_float2(u10 + hv1.x, u11 + hv1.y);
    }
    if (blockIdx.x == 0 && tid == 0) {
        float klv = (float)(g_kl / ((double)NN * (double)NN));
        for (int i = NHID; i < out_size; i++) out[i] = klv;
    }
}

// ---------------- launch ----------------
extern "C" void kernel_launch(void* const* d_in, const int* in_sizes, int n_in,
                              void* d_out, int out_size) {
    const float* h     = (const float*)d_in[0];
    const float* gamma = (const float*)d_in[1];
    const float* beta  = (const float*)d_in[2];
    const float* Wk    = (const float*)d_in[3];
    const float* bk    = (const float*)d_in[4];
    const float* Wm    = (const float*)d_in[5];
    const float* bm    = (const float*)d_in[6];
    const float* Wl    = (const float*)d_in[7];
    const float* bl    = (const float*)d_in[8];
    const float* Wv    = (const float*)d_in[9];
    const float* bv    = (const float*)d_in[10];
    const float* diff  = (const float*)d_in[11];
    const float* eps   = (const float*)d_in[12];
    float* out = (float*)d_out;

    cudaFuncSetAttribute(attn_kernel, cudaFuncAttributeMaxDynamicSharedMemorySize,
                         ATTN_SMEM_BYTES);
    cudaFuncSetAttribute(proj_kernel, cudaFuncAttributeMaxDynamicSharedMemorySize,
                         PROJ_SMEM);
    cudaFuncSetAttribute(final_kernel, cudaFuncAttributeMaxDynamicSharedMemorySize,
                         FIN_SMEM);

    prep_kernel<<<NN + 192 + 256, 256>>>(h, gamma, beta, Wk, Wm, Wl, Wv);
    dim3 gp(NN/64, 3);
    proj_kernel<<<gp, 256, PROJ_SMEM>>>(bk, bm, bl);
    attn_kernel<<<(NN/32)*NSPLIT, 256, ATTN_SMEM_BYTES>>>(diff, eps);
    final_kernel<<<NN/16, 256, FIN_SMEM>>>(bv, h, out, out_size);
}

// round 15
// speedup vs baseline: 1.0588x; 1.0588x over previous
#include <cuda_runtime.h>
#include <cuda_bf16.h>
#include <stdint.h>
#include <math.h>

#define NN 3072
#define HH 256
#define HD 64
#define NHID (NN*HH)
#define NSPLIT 3
#define ZRANGE (NN/NSPLIT)   // 1024
#define ZTILE 32
#define NZI (ZRANGE/ZTILE)   // 32
#define SCALE 0.125f         // HD^-0.5
#define PSTRIDE 72

// ---------------- device scratch (static; no allocations) ----------------
__device__ __nv_bfloat16 g_hnB[NHID];
__device__ __nv_bfloat16 g_hnT[HH*NN];
__device__ __nv_bfloat16 g_kt[4*NN*HD];
__device__ __nv_bfloat16 g_mut[4*NN*HD];
__device__ __nv_bfloat16 g_lst[4*NN*HD];
__device__ __nv_bfloat16 g_WT[3*HH*HH];
__device__ __nv_bfloat16 g_WvT[16*256*PSTRIDE];
__device__ float g_acc[(size_t)NN*1024];
__device__ float g_den[NN*4];
__device__ double g_kl;

// ---------------- PTX helpers ----------------
__device__ __forceinline__ void mma16816(float d[4], const uint32_t a[4],
                                         uint32_t b0, uint32_t b1) {
    asm volatile(
        "mma.sync.aligned.m16n8k16.row.col.f32.bf16.bf16.f32 "
        "{%0,%1,%2,%3},{%4,%5,%6,%7},{%8,%9},{%0,%1,%2,%3};\n"
        : "+f"(d[0]), "+f"(d[1]), "+f"(d[2]), "+f"(d[3])
        : "r"(a[0]), "r"(a[1]), "r"(a[2]), "r"(a[3]), "r"(b0), "r"(b1));
}
__device__ __forceinline__ void ldsm4(uint32_t r[4], uint32_t saddr) {
    asm volatile("ldmatrix.sync.aligned.m8n8.x4.shared.b16 {%0,%1,%2,%3}, [%4];\n"
        : "=r"(r[0]), "=r"(r[1]), "=r"(r[2]), "=r"(r[3]) : "r"(saddr));
}
__device__ __forceinline__ void cp16(uint32_t saddr, const void* g) {
    asm volatile("cp.async.cg.shared.global [%0], [%1], 16;\n" :: "r"(saddr), "l"(g));
}
#define CP_COMMIT() asm volatile("cp.async.commit_group;\n" ::: "memory")
#define CP_WAIT(n)  asm volatile("cp.async.wait_group %0;\n" :: "n"(n) : "memory")
__device__ __forceinline__ uint32_t s32(const void* p) {
    return (uint32_t)__cvta_generic_to_shared(p);
}
__device__ __forceinline__ void bulkcp(uint32_t dst, const void* src, uint32_t bytes,
                                       uint32_t mbar) {
    asm volatile("cp.async.bulk.shared::cluster.global.mbarrier::complete_tx::bytes "
                 "[%0], [%1], %2, [%3];\n"
                 :: "r"(dst), "l"(src), "r"(bytes), "r"(mbar) : "memory");
}
__device__ __forceinline__ void mbar_init(uint32_t m, uint32_t cnt) {
    asm volatile("mbarrier.init.shared.b64 [%0], %1;\n" :: "r"(m), "r"(cnt) : "memory");
}
__device__ __forceinline__ void mbar_expect(uint32_t m, uint32_t bytes) {
    asm volatile("mbarrier.arrive.expect_tx.shared.b64 _, [%0], %1;\n"
                 :: "r"(m), "r"(bytes) : "memory");
}
__device__ __forceinline__ void mbar_wait(uint32_t m, uint32_t parity) {
    uint32_t done;
    do {
        asm volatile("{\n.reg .pred p;\n"
                     "mbarrier.try_wait.parity.acquire.cta.shared::cta.b64 p, [%1], %2, 0x989680;\n"
                     "selp.b32 %0,1,0,p;\n}"
                     : "=r"(done) : "r"(m), "r"(parity) : "memory");
    } while (!done);
}
// vectorized global reduction: one RED.64 instead of two RED.32
__device__ __forceinline__ void red2(float* g, float a, float b) {
    asm volatile("red.global.add.v2.f32 [%0], {%1,%2};\n"
                 :: "l"(g), "f"(a), "f"(b) : "memory");
}

// ---------------- prep: LayerNorm + weight transposes + accumulator zeroing ----------------
__global__ void __launch_bounds__(256) prep_kernel(const float* __restrict__ h,
                                                   const float* __restrict__ gamma,
                                                   const float* __restrict__ beta,
                                                   const float* __restrict__ Wk,
                                                   const float* __restrict__ Wm,
                                                   const float* __restrict__ Wl,
                                                   const float* __restrict__ Wv) {
    __shared__ float sh[32][33];
    int bx = blockIdx.x, t = threadIdx.x;
    if (bx < NN) {
        int n = bx;
        *(float4*)(g_acc + (size_t)n*1024 + t*4) = make_float4(0.f,0.f,0.f,0.f);
        if (t == 0) *(float4*)(g_den + n*4) = make_float4(0.f,0.f,0.f,0.f);
        float v = h[n*HH + t];
        float s = v, q = v*v;
        #pragma unroll
        for (int o = 16; o; o >>= 1) {
            s += __shfl_down_sync(0xffffffffu, s, o);
            q += __shfl_down_sync(0xffffffffu, q, o);
        }
        __shared__ float ss[8], qs[8];
        __shared__ float s_m, s_r;
        int lane = t & 31, w = t >> 5;
        if (lane == 0) { ss[w] = s; qs[w] = q; }
        __syncthreads();
        if (t == 0) {
            float S = 0.f, Q = 0.f;
            #pragma unroll
            for (int i = 0; i < 8; i++) { S += ss[i]; Q += qs[i]; }
            float m = S * (1.f/256.f);
            float var = Q * (1.f/256.f) - m*m;
            s_m = m; s_r = rsqrtf(var + 1e-5f);
        }
        __syncthreads();
        float hn = (v - s_m) * s_r * gamma[t] + beta[t];
        __nv_bfloat16 hb = __float2bfloat16(hn);
        g_hnB[(size_t)n*HH + t] = hb;
        g_hnT[(size_t)t*NN + n] = hb;
        if (n == 0 && t == 0) g_kl = 0.0;
    } else {
        int tb = bx - NN;
        int tx = t & 31, ty = t >> 5;
        if (tb < 192) {
            int p = tb >> 6, tl = tb & 63;
            const float* src = (p == 0) ? Wk : (p == 1) ? Wm : Wl;
            __nv_bfloat16* dst = g_WT + (size_t)p*HH*HH;
            int o0 = (tl & 7)*32, k0 = (tl >> 3)*32;
            #pragma unroll
            for (int j = 0; j < 32; j += 8)
                sh[ty+j][tx] = src[(size_t)(k0+ty+j)*HH + o0+tx];
            __syncthreads();
            #pragma unroll
            for (int j = 0; j < 32; j += 8)
                dst[(size_t)(o0+ty+j)*HH + k0+tx] = __float2bfloat16(sh[tx][ty+j]);
        } else {
            int tl = tb - 192;
            int o0 = (tl & 7)*32, k0 = (tl >> 3)*32;
            #pragma unroll
            for (int j = 0; j < 32; j += 8)
                sh[ty+j][tx] = Wv[(size_t)(k0+ty+j)*HH + o0+tx];
            __syncthreads();
            #pragma unroll
            for (int j = 0; j < 32; j += 8) {
                int o = o0+ty+j, k = k0+tx;
                g_WvT[(size_t)(k >> 6)*(256*PSTRIDE) + o*PSTRIDE + (k & 63)] =
                    __float2bfloat16(sh[tx][ty+j]);
            }
        }
    }
}

// ---------------- 3 projections (bf16 HMMA) -> head-transposed bf16 ----------------
#define PROJ_SMEM ((64*264 + 256*72)*2)
__global__ void __launch_bounds__(256) proj_kernel(const float* __restrict__ bk,
                                                   const float* __restrict__ bm,
                                                   const float* __restrict__ bl) {
    extern __shared__ __nv_bfloat16 ps[];
    __nv_bfloat16* a_s = ps;
    __nv_bfloat16* b_s = ps + 64*264;
    int p = blockIdx.y;
    const __nv_bfloat16* WT = g_WT + (size_t)p*HH*HH;
    const float* bi = (p == 0) ? bk : (p == 1) ? bm : bl;
    __nv_bfloat16* dst = (p == 0) ? g_kt : (p == 1) ? g_mut : g_lst;
    int tid = threadIdx.x;
    int r0 = blockIdx.x * 64;

    #pragma unroll
    for (int j = 0; j < 8; j++) {
        int idx = j*256 + tid; int row = idx >> 5, u = idx & 31;
        *(uint4*)(a_s + row*264 + u*8) =
            *(const uint4*)(g_hnB + (size_t)(r0+row)*HH + u*8);
    }

    int w = tid >> 5, l = tid & 31, t2 = (l & 3)*2, g = l >> 2;
    int wm = w >> 1, wn = w & 1;
    uint32_t a_base = s32(a_s) + (uint32_t)(((wm*16 + (l & 15))*264 + (l >> 4)*8) * 2);
    uint32_t b_base = s32(b_s) + (uint32_t)((((l >> 4)*8 + (l & 7))*72 + ((l >> 3) & 1)*8) * 2);
    float acc[16][4];
    #pragma unroll
    for (int nt = 0; nt < 16; nt++) { acc[nt][0]=0.f; acc[nt][1]=0.f; acc[nt][2]=0.f; acc[nt][3]=0.f; }

    for (int kc = 0; kc < 4; kc++) {
        __syncthreads();
        #pragma unroll
        for (int j = 0; j < 8; j++) {
            int idx = j*256 + tid; int o = idx >> 3, u = idx & 7;
            *(uint4*)(b_s + o*72 + u*8) =
                *(const uint4*)(WT + (size_t)o*HH + kc*64 + u*8);
        }
        __syncthreads();
        #pragma unroll
        for (int k16 = 0; k16 < 4; k16++) {
            uint32_t a[4];
            ldsm4(a, a_base + (uint32_t)((kc*64 + k16*16)*2));
            #pragma unroll
            for (int ntp = 0; ntp < 8; ntp++) {
                uint32_t bb[4];
                ldsm4(bb, b_base + (uint32_t)(((wn*128 + ntp*16)*72 + k16*16)*2));
                mma16816(acc[ntp*2],   a, bb[0], bb[1]);
                mma16816(acc[ntp*2+1], a, bb[2], bb[3]);
            }
        }
    }

    #pragma unroll
    for (int nt = 0; nt < 16; nt++) {
        int oc = wn*128 + nt*8 + t2;
        float b0v = bi[oc], b1v = bi[oc+1];
        int m0 = r0 + wm*16 + g, m1 = m0 + 8;
        dst[((size_t)(oc & 3)*NN + m0)*HD + (oc >> 2)]         = __float2bfloat16(acc[nt][0] + b0v);
        dst[((size_t)((oc+1) & 3)*NN + m0)*HD + ((oc+1) >> 2)] = __float2bfloat16(acc[nt][1] + b1v);
        dst[((size_t)(oc & 3)*NN + m1)*HD + (oc >> 2)]         = __float2bfloat16(acc[nt][2] + b0v);
        dst[((size_t)((oc+1) & 3)*NN + m1)*HD + ((oc+1) >> 2)] = __float2bfloat16(acc[nt][3] + b1v);
    }
}

// ---------------- fused attention: champion + vectorized reductions ----------------
#define K_S_ELEMS  (4*32*72)
#define MU_BUF     (4*ZTILE*72)
#define HN_STRIDE  40
#define HN_BUF     (256*HN_STRIDE)
#define AF_BUF     (128*40)
#define BF_ELEMS   (K_S_ELEMS + 2*MU_BUF + 2*MU_BUF + 2*HN_BUF + AF_BUF)
#define EPS_STRIDE 132
#define DIF_STRIDE 36
#define EPS_BUF (32*EPS_STRIDE)
#define DIF_BUF (32*DIF_STRIDE)
#define ATTN_SMEM_BYTES (BF_ELEMS*2 + (2*EPS_BUF + 2*DIF_BUF)*4)

__global__ void __launch_bounds__(256, 1) attn_kernel(const float* __restrict__ diff,
                                                      const float* __restrict__ eps) {
    extern __shared__ __nv_bfloat16 smb[];
    __nv_bfloat16* k_s  = smb;
    __nv_bfloat16* mu_s = k_s + K_S_ELEMS;
    __nv_bfloat16* ls_s = mu_s + 2*MU_BUF;
    __nv_bfloat16* hn_s = ls_s + 2*MU_BUF;
    float* eps_s = (float*)(smb + BF_ELEMS);
    float* dif_s = eps_s + 2*EPS_BUF;
    __shared__ float red[8];

    const int tid = threadIdx.x;
    const int xt = blockIdx.x / NSPLIT, sp = blockIdx.x % NSPLIT;
    const int x0 = xt * 32, zbase = sp * ZRANGE;
    const int w = tid >> 5, l = tid & 31;
    const int b = w >> 1, xh = w & 1;
    const int g = l >> 2, t2 = (l & 3) * 2;

    const uint32_t mu_fb = s32(mu_s) + (uint32_t)(((b*32 + (l & 7))*72 + (l >> 3)*8) * 2);
    const uint32_t ls_fb = s32(ls_s) + (uint32_t)(((b*32 + (l & 7))*72 + (l >> 3)*8) * 2);
    const uint32_t hn_fb = s32(hn_s) + (uint32_t)((((l >> 4)*8 + (l & 7))*HN_STRIDE + ((l >> 3) & 1)*8) * 2);

    auto stage = [&](int zb, int cb) {
        __nv_bfloat16* mb_ = mu_s + cb*MU_BUF;
        __nv_bfloat16* lb_ = ls_s + cb*MU_BUF;
        __nv_bfloat16* hb_ = hn_s + cb*HN_BUF;
        float* eb_ = eps_s + cb*EPS_BUF;
        float* db_ = dif_s + cb*DIF_BUF;
        #pragma unroll
        for (int j = 0; j < 4; j++) {
            int idx = j*256 + tid; int row = idx >> 3, u = idx & 7;
            int bb_ = row >> 5, z_ = row & 31;
            cp16(s32(mb_ + row*72 + u*8), g_mut + ((size_t)bb_*NN + zb + z_)*HD + u*8);
            cp16(s32(lb_ + row*72 + u*8), g_lst + ((size_t)bb_*NN + zb + z_)*HD + u*8);
        }
        #pragma unroll
        for (int j = 0; j < 4; j++) {
            int idx = j*256 + tid; int row = idx >> 2, u = idx & 3;
            cp16(s32(hb_ + row*HN_STRIDE + u*8), g_hnT + (size_t)row*NN + zb + u*8);
        }
        #pragma unroll
        for (int j = 0; j < 4; j++) {
            int idx = j*256 + tid; int x = idx >> 5, u = idx & 31;
            cp16(s32(eb_ + x*EPS_STRIDE + u*4), eps + ((size_t)(x0+x)*NN + zb)*4 + u*4);
        }
        {
            int x = tid >> 3, u = tid & 7;
            cp16(s32(db_ + x*DIF_STRIDE + u*4), diff + (size_t)(x0+x)*NN + zb + u*4);
        }
    };

    #pragma unroll
    for (int j = 0; j < 4; j++) {
        int idx = j*256 + tid; int row = idx >> 3, u = idx & 7;
        int br = row >> 5, xr = row & 31;
        cp16(s32(k_s + (br*32 + xr)*72 + u*8),
             g_kt + ((size_t)br*NN + x0 + xr)*HD + u*8);
    }
    stage(zbase, 0);
    CP_COMMIT();

    float acc[32][4];
    #pragma unroll
    for (int nt = 0; nt < 32; nt++) { acc[nt][0]=0.f; acc[nt][1]=0.f; acc[nt][2]=0.f; acc[nt][3]=0.f; }
    float den0 = 0.f, den1 = 0.f, klloc = 0.f;
    uint32_t kfr[4][4];

    for (int zi = 0; zi < NZI; ++zi) {
        __syncthreads();
        if (zi + 1 < NZI) {
            stage(zbase + (zi+1)*ZTILE, (zi+1) & 1);
            CP_COMMIT();
            CP_WAIT(1);
        } else {
            CP_WAIT(0);
        }
        __syncthreads();

        if (zi == 0) {
            #pragma unroll
            for (int kt = 0; kt < 4; kt++) {
                const __nv_bfloat16* base = k_s + (b*32 + xh*16)*72 + kt*16;
                kfr[kt][0] = *(const uint32_t*)(base + (size_t)g*72     + t2);
                kfr[kt][1] = *(const uint32_t*)(base + (size_t)(g+8)*72 + t2);
                kfr[kt][2] = *(const uint32_t*)(base + (size_t)g*72     + t2 + 8);
                kfr[kt][3] = *(const uint32_t*)(base + (size_t)(g+8)*72 + t2 + 8);
            }
        }
        const int cb = zi & 1;
        const float* ecur = eps_s + cb*EPS_BUF;
        const float* dcur = dif_s + cb*DIF_BUF;
        const uint32_t mu_base = mu_fb + (uint32_t)((cb*MU_BUF)*2);
        const uint32_t ls_base = ls_fb + (uint32_t)((cb*MU_BUF)*2);
        const uint32_t hn_base = hn_fb + (uint32_t)((cb*HN_BUF)*2);

        #pragma unroll
        for (int zk = 0; zk < 2; zk++) {
            float dmu[2][4], dls[2][4];
            #pragma unroll
            for (int t = 0; t < 2; t++) {
                dmu[t][0]=0.f; dmu[t][1]=0.f; dmu[t][2]=0.f; dmu[t][3]=0.f;
                dls[t][0]=0.f; dls[t][1]=0.f; dls[t][2]=0.f; dls[t][3]=0.f;
                uint32_t roff = (uint32_t)(((zk*16 + t*8)*72) * 2);
                uint32_t mb[4], lb[4];
                ldsm4(mb, mu_base + roff);
                mma16816(dmu[t], kfr[0], mb[0], mb[1]);
                mma16816(dmu[t], kfr[1], mb[2], mb[3]);
                ldsm4(mb, mu_base + roff + 64);
                mma16816(dmu[t], kfr[2], mb[0], mb[1]);
                mma16816(dmu[t], kfr[3], mb[2], mb[3]);
                ldsm4(lb, ls_base + roff);
                mma16816(dls[t], kfr[0], lb[0], lb[1]);
                mma16816(dls[t], kfr[1], lb[2], lb[3]);
                ldsm4(lb, ls_base + roff + 64);
                mma16816(dls[t], kfr[2], lb[0], lb[1]);
                mma16816(dls[t], kfr[3], lb[2], lb[3]);
            }
            uint32_t af[4];
            #pragma unroll
            for (int t = 0; t < 2; t++) {
                #pragma unroll
                for (int rr = 0; rr < 2; rr++) {
                    int lx = xh*16 + rr*8 + g;
                    int lz = zk*16 + t*8 + t2;
                    float2 dv = *(const float2*)(dcur + lx*DIF_STRIDE + lz);
                    const float* ep = ecur + lx*EPS_STRIDE + lz*4 + b;
                    float e0 = ep[0], e1 = ep[4];
                    float m0 = dmu[t][rr*2]   * SCALE;
                    float m1 = dmu[t][rr*2+1] * SCALE;
                    float s0 = dls[t][rr*2]   * SCALE;
                    float s1 = dls[t][rr*2+1] * SCALE;
                    float sg0 = __logf(1.f + __expf(s0));
                    float sg1 = __logf(1.f + __expf(s1));
                    float d0 = dv.x, d1 = dv.y;
                    float a0 = __expf(fmaf(sg0, e0, m0)) * d0;
                    float a1 = __expf(fmaf(sg1, e1, m1)) * d1;
                    float sn0 = (d0 > 0.f) ? 1.f : ((d0 < 0.f) ? -1.f : 0.f);
                    float sn1 = (d1 > 0.f) ? 1.f : ((d1 < 0.f) ? -1.f : 0.f);
                    klloc += sn0 * (0.5f*(sg0*sg0 + m0*m0) - 0.5f - __logf(sg0));
                    klloc += sn1 * (0.5f*(sg1*sg1 + m1*m1) - 0.5f - __logf(sg1));
                    if (rr == 0) den0 += a0 + a1; else den1 += a0 + a1;
                    __nv_bfloat162 p = __float22bfloat162_rn(make_float2(a0, a1));
                    af[t*2 + rr] = *(uint32_t*)&p;
                }
            }
            #pragma unroll
            for (int ntp = 0; ntp < 16; ntp++) {
                uint32_t hb[4];
                ldsm4(hb, hn_base + (uint32_t)((ntp*16*HN_STRIDE + zk*16)*2));
                mma16816(acc[ntp*2],     af, hb[0], hb[1]);
                mma16816(acc[ntp*2 + 1], af, hb[2], hb[3]);
            }
        }
    }

    // ---- epilogue: vectorized atomic accumulation (RED.64) ----
    {
        const int xr_lo = x0 + xh*16 + g;
        float* outlo = g_acc + (size_t)xr_lo*1024 + b*256;
        float* outhi = outlo + (size_t)8*1024;
        #pragma unroll
        for (int nt = 0; nt < 32; nt++) {
            red2(outlo + nt*8 + t2, acc[nt][0], acc[nt][1]);
            red2(outhi + nt*8 + t2, acc[nt][2], acc[nt][3]);
        }
        den0 += __shfl_xor_sync(0xffffffffu, den0, 1);
        den0 += __shfl_xor_sync(0xffffffffu, den0, 2);
        den1 += __shfl_xor_sync(0xffffffffu, den1, 1);
        den1 += __shfl_xor_sync(0xffffffffu, den1, 2);
        if ((l & 3) == 0) {
            atomicAdd(g_den + (x0 + xh*16 + g)*4 + b,     den0);
            atomicAdd(g_den + (x0 + xh*16 + 8 + g)*4 + b, den1);
        }
    }
    #pragma unroll
    for (int o = 16; o; o >>= 1) klloc += __shfl_down_sync(0xffffffffu, klloc, o);
    if (l == 0) red[w] = klloc;
    __syncthreads();
    if (tid == 0) {
        float s = 0.f;
        #pragma unroll
        for (int i = 0; i < 8; i++) s += red[i];
        atomicAdd(&g_kl, (double)s);
    }
}

// ---------------- normalize + fc_v (bf16 HMMA, bulk W_v staging) ----------------
#define WV_BUF (256*72)
#define FIN_SMEM ((16*1032 + 2*WV_BUF)*2)
__global__ void __launch_bounds__(256) final_kernel(const float* __restrict__ bv,
                                                    const float* __restrict__ h0,
                                                    float* __restrict__ out,
                                                    int out_size) {
    extern __shared__ __nv_bfloat16 fs[];
    __nv_bfloat16* vsb  = fs;
    __nv_bfloat16* wv_s = fs + 16*1032;
    __shared__ alignas(8) uint64_t fmbar[2];
    int tid = threadIdx.x;
    int r0 = blockIdx.x * 16;
    const uint32_t mb0 = s32(&fmbar[0]), mb1 = s32(&fmbar[1]);

    if (tid == 0) { mbar_init(mb0, 1); mbar_init(mb1, 1); }
    __syncthreads();
    if (tid == 0) {
        mbar_expect(mb0, 36864);
        bulkcp(s32(wv_s), g_WvT, 36864, mb0);
    }

    #pragma unroll
    for (int ii = 0; ii < 16; ii++) {
        int idx = ii*256 + tid;
        int r = idx >> 8, c4 = idx & 255;
        int n = r0 + r;
        float4 a0 = *((const float4*)(g_acc + (size_t)n*1024) + c4);
        int b = c4 >> 6;
        float inv = 1.f / fmaxf(g_den[n*4 + b], 1e-12f);
        __nv_bfloat162 p0 = __float22bfloat162_rn(make_float2(a0.x*inv, a0.y*inv));
        __nv_bfloat162 p1 = __float22bfloat162_rn(make_float2(a0.z*inv, a0.w*inv));
        *(uint32_t*)(vsb + r*1032 + c4*4)     = *(uint32_t*)&p0;
        *(uint32_t*)(vsb + r*1032 + c4*4 + 2) = *(uint32_t*)&p1;
    }

    int w = tid >> 5, l = tid & 31, g = l >> 2, t2 = (l & 3)*2;
    int n0 = w * 32;
    uint32_t a_base = s32(vsb)  + (uint32_t)(((l & 15)*1032 + (l >> 4)*8) * 2);
    uint32_t b_base = s32(wv_s) + (uint32_t)((((l >> 4)*8 + (l & 7))*72 + ((l >> 3) & 1)*8) * 2);
    float acc[4][4];
    #pragma unroll
    for (int nt = 0; nt < 4; nt++) { acc[nt][0]=0.f; acc[nt][1]=0.f; acc[nt][2]=0.f; acc[nt][3]=0.f; }

    __syncthreads();

    for (int kc = 0; kc < 16; kc++) {
        __syncthreads();
        if (tid == 0 && kc + 1 < 16) {
            uint32_t m = ((kc+1) & 1) ? mb1 : mb0;
            mbar_expect(m, 36864);
            bulkcp(s32(wv_s + ((kc+1) & 1)*WV_BUF), g_WvT + (size_t)(kc+1)*WV_BUF, 36864, m);
        }
        mbar_wait((kc & 1) ? mb1 : mb0, (kc >> 1) & 1);

        uint32_t boff = (uint32_t)(((kc & 1)*WV_BUF)*2);
        #pragma unroll
        for (int k16 = 0; k16 < 4; k16++) {
            uint32_t a[4];
            ldsm4(a, a_base + (uint32_t)((kc*64 + k16*16)*2));
            #pragma unroll
            for (int ntp = 0; ntp < 2; ntp++) {
                uint32_t bb[4];
                ldsm4(bb, b_base + boff + (uint32_t)(((n0 + ntp*16)*72 + k16*16)*2));
                mma16816(acc[ntp*2],   a, bb[0], bb[1]);
                mma16816(acc[ntp*2+1], a, bb[2], bb[3]);
            }
        }
    }

    #pragma unroll
    for (int nt = 0; nt < 4; nt++) {
        int oc = n0 + nt*8 + t2;
        float b0v = bv[oc], b1v = bv[oc+1];
        int m0 = r0 + g, m1 = m0 + 8;
        float u00 = acc[nt][0] + b0v, u01 = acc[nt][1] + b1v;
        float u10 = acc[nt][2] + b0v, u11 = acc[nt][3] + b1v;
        u00 = (u00 > 0.f) ? u00 : expm1f(u00);
        u01 = (u01 > 0.f) ? u01 : expm1f(u01);
        u10 = (u10 > 0.f) ? u10 : expm1f(u10);
        u11 = (u11 > 0.f) ? u11 : expm1f(u11);
        float2 hv0 = *(const float2*)(h0 + (size_t)m0*HH + oc);
        float2 hv1 = *(const float2*)(h0 + (size_t)m1*HH + oc);
        *(float2*)(out + (size_t)m0*HH + oc) = make_float2(u00 + hv0.x, u01 + hv0.y);
        *(float2*)(out + (size_t)m1*HH + oc) = make_float2(u10 + hv1.x, u11 + hv1.y);
    }
    if (blockIdx.x == 0 && tid == 0) {
        float klv = (float)(g_kl / ((double)NN * (double)NN));
        for (int i = NHID; i < out_size; i++) out[i] = klv;
    }
}

// ---------------- launch ----------------
extern "C" void kernel_launch(void* const* d_in, const int* in_sizes, int n_in,
                              void* d_out, int out_size) {
    const float* h     = (const float*)d_in[0];
    const float* gamma = (const float*)d_in[1];
    const float* beta  = (const float*)d_in[2];
    const float* Wk    = (const float*)d_in[3];
    const float* bk    = (const float*)d_in[4];
    const float* Wm    = (const float*)d_in[5];
    const float* bm    = (const float*)d_in[6];
    const float* Wl    = (const float*)d_in[7];
    const float* bl    = (const float*)d_in[8];
    const float* Wv    = (const float*)d_in[9];
    const float* bv    = (const float*)d_in[10];
    const float* diff  = (const float*)d_in[11];
    const float* eps   = (const float*)d_in[12];
    float* out = (float*)d_out;

    cudaFuncSetAttribute(attn_kernel, cudaFuncAttributeMaxDynamicSharedMemorySize,
                         ATTN_SMEM_BYTES);
    cudaFuncSetAttribute(proj_kernel, cudaFuncAttributeMaxDynamicSharedMemorySize,
                         PROJ_SMEM);
    cudaFuncSetAttribute(final_kernel, cudaFuncAttributeMaxDynamicSharedMemorySize,
                         FIN_SMEM);

    prep_kernel<<<NN + 192 + 256, 256>>>(h, gamma, beta, Wk, Wm, Wl, Wv);
    dim3 gp(NN/64, 3);
    proj_kernel<<<gp, 256, PROJ_SMEM>>>(bk, bm, bl);
    attn_kernel<<<(NN/32)*NSPLIT, 256, ATTN_SMEM_BYTES>>>(diff, eps);
    final_kernel<<<NN/16, 256, FIN_SMEM>>>(bv, h, out, out_size);
}